// round 7
// baseline (speedup 1.0000x reference)
#include <cuda_runtime.h>
#include <cstdint>

#define D_DIM 256
#define N_MAX 4096
#define M_MAX 16384
#define EPSV 1e-12f

// ---------------------------------------------------------------------------
// Scratch (static device arrays; no allocations allowed).
// ---------------------------------------------------------------------------
__device__ float g_x2[N_MAX];
__device__ float g_y2[M_MAX];
__device__ float g_rowsum[N_MAX];
__device__ __align__(16) uint32_t g_X8[N_MAX * (D_DIM / 4)];   // e4m3 packed x4
__device__ __align__(16) uint32_t g_Y8[M_MAX * (D_DIM / 4)];   // e4m3 packed x4

// ---------------------------------------------------------------------------
// PTX helpers
// ---------------------------------------------------------------------------
__device__ __forceinline__ uint32_t smem_u32(const void* p) {
    uint32_t a;
    asm("{ .reg .u64 t; cvta.to.shared.u64 t, %1; cvt.u32.u64 %0, t; }" : "=r"(a) : "l"(p));
    return a;
}
#define CP_ASYNC16(dst, src) asm volatile("cp.async.cg.shared.global [%0], [%1], 16;" :: "r"(dst), "l"(src) : "memory")
#define CP_COMMIT()          asm volatile("cp.async.commit_group;" ::: "memory")
#define CP_WAIT0()           asm volatile("cp.async.wait_group 0;" ::: "memory")

__device__ __forceinline__ void ldmatrix_x4(uint32_t* r, uint32_t addr) {
    asm volatile("ldmatrix.sync.aligned.m8n8.x4.shared.b16 {%0,%1,%2,%3}, [%4];"
                 : "=r"(r[0]), "=r"(r[1]), "=r"(r[2]), "=r"(r[3]) : "r"(addr));
}
// fp8 e4m3 MMA, k32
__device__ __forceinline__ void mma_fp8(float* c, const uint32_t* a, const uint32_t* b) {
    asm volatile("mma.sync.aligned.m16n8k32.row.col.f32.e4m3.e4m3.f32 "
                 "{%0,%1,%2,%3}, {%4,%5,%6,%7}, {%8,%9}, {%0,%1,%2,%3};"
                 : "+f"(c[0]), "+f"(c[1]), "+f"(c[2]), "+f"(c[3])
                 : "r"(a[0]), "r"(a[1]), "r"(a[2]), "r"(a[3]), "r"(b[0]), "r"(b[1]));
}

// ---------------------------------------------------------------------------
__global__ void zero_kernel(float* out, int N) {
    int t = blockIdx.x * blockDim.x + threadIdx.x;
    if (t < N) g_rowsum[t] = 0.0f;
    if (t == 0) out[0] = 0.0f;
}

// ---------------------------------------------------------------------------
// Fused prep: fp32 -> e4m3 pack + squared norms (fp32 exact), one warp/row.
// Thread handles k = 8*lane .. 8*lane+7 (two float4) -> 8 bytes out.
// ---------------------------------------------------------------------------
__global__ void prep_kernel(const float* __restrict__ X,
                            const float* __restrict__ Y, int N, int M) {
    int warp = (blockIdx.x * blockDim.x + threadIdx.x) >> 5;
    int lane = threadIdx.x & 31;
    if (warp >= N + M) return;
    const float4* src; uint2* dst; float* nrm; int row;
    if (warp < N) { src = (const float4*)X; dst = (uint2*)g_X8; nrm = g_x2; row = warp; }
    else          { src = (const float4*)Y; dst = (uint2*)g_Y8; nrm = g_y2; row = warp - N; }

    float4 v1 = src[row * 64 + 2 * lane];
    float4 v2 = src[row * 64 + 2 * lane + 1];
    float s = v1.x*v1.x + v1.y*v1.y + v1.z*v1.z + v1.w*v1.w
            + v2.x*v2.x + v2.y*v2.y + v2.z*v2.z + v2.w*v2.w;
#pragma unroll
    for (int o = 16; o; o >>= 1) s += __shfl_xor_sync(0xffffffffu, s, o);
    if (lane == 0) nrm[row] = s;

    uint16_t h0, h1, h2, h3;
    asm("cvt.rn.satfinite.e4m3x2.f32 %0, %1, %2;" : "=h"(h0) : "f"(v1.y), "f"(v1.x));
    asm("cvt.rn.satfinite.e4m3x2.f32 %0, %1, %2;" : "=h"(h1) : "f"(v1.w), "f"(v1.z));
    asm("cvt.rn.satfinite.e4m3x2.f32 %0, %1, %2;" : "=h"(h2) : "f"(v2.y), "f"(v2.x));
    asm("cvt.rn.satfinite.e4m3x2.f32 %0, %1, %2;" : "=h"(h3) : "f"(v2.w), "f"(v2.z));
    uint2 p;
    asm("mov.b32 %0, {%1, %2};" : "=r"(p.x) : "h"(h0), "h"(h1));
    asm("mov.b32 %0, {%1, %2};" : "=r"(p.y) : "h"(h2), "h"(h3));
    dst[row * 32 + lane] = p;
}

// ---------------------------------------------------------------------------
// Fused distance GEMM via mma.sync fp8 e4m3 (k32).
// CTA 128x128, occ 2; K=256 in 2 chunks of 128 fp8 (144B padded rows),
// double-buffered cp.async. 8 warps in 2(m) x 4(n): warp tile 64x32.
// fp8-as-b16 ldmatrix: identical address math to the bf16 version.
// ---------------------------------------------------------------------------
#define ROWB   144
#define TILE_B (128 * ROWB)
#define OFF_A  0
#define OFF_B  (2 * TILE_B)
#define OFF_X2 (4 * TILE_B)
#define OFF_Y2 (4 * TILE_B + 512)
#define OFF_RED (4 * TILE_B + 1024)
#define SMEM_DYN (4 * TILE_B + 1536)

__global__ __launch_bounds__(256, 2)
void dist_kernel(int N, int M) {
    extern __shared__ __align__(16) char smem[];
    const uint32_t sbase = smem_u32(smem);
    float* x2s = (float*)(smem + OFF_X2);
    float* y2s = (float*)(smem + OFF_Y2);
    float* red = (float*)(smem + OFF_RED);

    const int tid  = threadIdx.x;
    const int wid  = tid >> 5;
    const int lane = tid & 31;
    const int iBase = blockIdx.y * 128;
    const int jBase = blockIdx.x * 128;
    const int iw = (wid >> 2) * 64;
    const int jw = (wid & 3) * 32;

    // row stride = 256 B = 16 uint4
    const uint4* Ag = (const uint4*)g_X8 + (size_t)iBase * 16;
    const uint4* Bg = (const uint4*)g_Y8 + (size_t)jBase * 16;

    float acc[4][4][4];
#pragma unroll
    for (int a = 0; a < 4; a++)
#pragma unroll
        for (int b = 0; b < 4; b++)
#pragma unroll
            for (int c = 0; c < 4; c++) acc[a][b][c] = 0.0f;

    if (tid < 128) x2s[tid] = g_x2[iBase + tid];
    else           y2s[tid - 128] = g_y2[jBase + tid - 128];
    if (tid < 128) red[tid] = 0.0f;

    // chunk = 128 fp8 per row = 8 x 16B quads; kq = chunk * 8
    auto load_tiles = [&](int buf, int kq) {
#pragma unroll
        for (int t = 0; t < 4; t++) {
            int idx = tid + t * 256;
            int row = idx >> 3, q = idx & 7;
            CP_ASYNC16(sbase + OFF_A + buf * TILE_B + row * ROWB + q * 16,
                       (const void*)(Ag + row * 16 + kq + q));
        }
#pragma unroll
        for (int t = 0; t < 4; t++) {
            int idx = tid + t * 256;
            int row = idx >> 3, q = idx & 7;
            CP_ASYNC16(sbase + OFF_B + buf * TILE_B + row * ROWB + q * 16,
                       (const void*)(Bg + row * 16 + kq + q));
        }
        CP_COMMIT();
    };

    load_tiles(0, 0);
    CP_WAIT0();
    __syncthreads();

    // ldmatrix address components (b16 view of fp8 pairs)
    const int aRow = lane & 15;
    const int aColSel = (lane >> 4) * 16;
    const int bRow = ((lane & 16) >> 1) + (lane & 7);
    const int bColSel = ((lane >> 3) & 1) * 16;

#pragma unroll
    for (int kt = 0; kt < 2; kt++) {
        const int buf = kt & 1;
        if (kt < 1) load_tiles(buf ^ 1, 8);

        const uint32_t sA = sbase + OFF_A + buf * TILE_B;
        const uint32_t sB = sbase + OFF_B + buf * TILE_B;
#pragma unroll
        for (int ks = 0; ks < 4; ks++) {     // k32 steps: 32 B each
            uint32_t afr[4][4], bfr[4][2];
#pragma unroll
            for (int mf = 0; mf < 4; mf++)
                ldmatrix_x4(afr[mf], sA + (iw + mf * 16 + aRow) * ROWB
                                        + ks * 32 + aColSel);
#pragma unroll
            for (int np = 0; np < 2; np++) {
                uint32_t r[4];
                ldmatrix_x4(r, sB + (jw + np * 16 + bRow) * ROWB
                                  + ks * 32 + bColSel);
                bfr[2*np][0]   = r[0]; bfr[2*np][1]   = r[1];
                bfr[2*np+1][0] = r[2]; bfr[2*np+1][1] = r[3];
            }
#pragma unroll
            for (int mf = 0; mf < 4; mf++)
#pragma unroll
                for (int nf = 0; nf < 4; nf++)
                    mma_fp8(acc[mf][nf], afr[mf], bfr[nf]);
        }
        if (kt < 1) { CP_WAIT0(); __syncthreads(); }
    }
    __syncthreads();

    // Epilogue: dist + per-row reduction.
#pragma unroll
    for (int mf = 0; mf < 4; mf++) {
        const int r0 = iw + mf * 16 + (lane >> 2);
        const float x20 = x2s[r0], x21 = x2s[r0 + 8];
        float rs0 = 0.0f, rs1 = 0.0f;
#pragma unroll
        for (int nf = 0; nf < 4; nf++) {
            const int j0 = jw + nf * 8 + (lane & 3) * 2;
            const float y20 = y2s[j0], y21 = y2s[j0 + 1];
            const float* c = acc[mf][nf];
            float d2;
            d2 = fmaxf(fmaf(-2.0f, c[0], x20 + y20), 0.0f) + EPSV; rs0 += d2 * rsqrtf(d2);
            d2 = fmaxf(fmaf(-2.0f, c[1], x20 + y21), 0.0f) + EPSV; rs0 += d2 * rsqrtf(d2);
            d2 = fmaxf(fmaf(-2.0f, c[2], x21 + y20), 0.0f) + EPSV; rs1 += d2 * rsqrtf(d2);
            d2 = fmaxf(fmaf(-2.0f, c[3], x21 + y21), 0.0f) + EPSV; rs1 += d2 * rsqrtf(d2);
        }
        rs0 += __shfl_xor_sync(0xffffffffu, rs0, 1);
        rs0 += __shfl_xor_sync(0xffffffffu, rs0, 2);
        rs1 += __shfl_xor_sync(0xffffffffu, rs1, 1);
        rs1 += __shfl_xor_sync(0xffffffffu, rs1, 2);
        if ((lane & 3) == 0) {
            atomicAdd(&red[r0], rs0);
            atomicAdd(&red[r0 + 8], rs1);
        }
    }
    __syncthreads();
    if (tid < 128) atomicAdd(&g_rowsum[iBase + tid], red[tid]);
}

// ---------------------------------------------------------------------------
// Exact loss, 2D grid: block (bx, by): i in [bx*256,+256), j in [by*256,+256).
// 256 blocks -> full-chip parallelism.
// ---------------------------------------------------------------------------
__global__ void loss_kernel(float* __restrict__ out, int N, float invM) {
    __shared__ __align__(16) float sj[256];
    __shared__ float wsum[8];
    const int tid = threadIdx.x;
    const int i  = blockIdx.x * 256 + tid;
    const int jb = blockIdx.y * 256;

    sj[tid] = g_rowsum[jb + tid] * invM;
    const float di = g_rowsum[i] * invM;
    __syncthreads();

    float local = 0.0f;
#pragma unroll 8
    for (int j = 0; j < 256; j += 4) {
        float4 v = *(const float4*)&sj[j];
        float df, s;
        df = di - v.x; s = df * df + EPSV; local += s * rsqrtf(s);
        df = di - v.y; s = df * df + EPSV; local += s * rsqrtf(s);
        df = di - v.z; s = df * df + EPSV; local += s * rsqrtf(s);
        df = di - v.w; s = df * df + EPSV; local += s * rsqrtf(s);
    }
#pragma unroll
    for (int o = 16; o; o >>= 1) local += __shfl_xor_sync(0xffffffffu, local, o);
    int lane = tid & 31, warp = tid >> 5;
    if (lane == 0) wsum[warp] = local;
    __syncthreads();
    if (tid == 0) {
        float s = 0.0f;
#pragma unroll
        for (int w = 0; w < 8; w++) s += wsum[w];
        atomicAdd(out, s);
    }
}

// ---------------------------------------------------------------------------
extern "C" void kernel_launch(void* const* d_in, const int* in_sizes, int n_in,
                              void* d_out, int out_size) {
    const float* X = (const float*)d_in[0];
    const float* Y = (const float*)d_in[1];
    float* out = (float*)d_out;
    const int N = in_sizes[0] / D_DIM;   // 4096
    const int M = in_sizes[1] / D_DIM;   // 16384

    static int attr_done = 0;
    if (!attr_done) {
        cudaFuncSetAttribute(dist_kernel,
                             cudaFuncAttributeMaxDynamicSharedMemorySize, SMEM_DYN);
        attr_done = 1;
    }

    zero_kernel<<<(N + 255) / 256, 256>>>(out, N);
    prep_kernel<<<((N + M) * 32 + 255) / 256, 256>>>(X, Y, N, M);
    dim3 grid(M / 128, N / 128);
    dist_kernel<<<grid, 256, SMEM_DYN>>>(N, M);
    dim3 lgrid(N / 256, N / 256);
    loss_kernel<<<lgrid, 256>>>(out, N, 1.0f / (float)M);
}

// round 8
// speedup vs baseline: 1.5169x; 1.5169x over previous
#include <cuda_runtime.h>
#include <cstdint>

#define D_DIM 256
#define N_MAX 4096
#define M_MAX 16384
#define EPSV 1e-12f

// ---------------------------------------------------------------------------
// Scratch (static device arrays; no allocations allowed).
// ---------------------------------------------------------------------------
__device__ float g_x2[N_MAX];
__device__ float g_y2[M_MAX];
__device__ float g_rowsum[N_MAX];
__device__ __align__(16) uint32_t g_Xh[N_MAX * (D_DIM / 2)];   // bf16x2 packed
__device__ __align__(16) uint32_t g_Yh[M_MAX * (D_DIM / 2)];   // bf16x2 packed

// ---------------------------------------------------------------------------
// PTX helpers (arch-portable: ldmatrix / mma.sync / cp.async)
// ---------------------------------------------------------------------------
__device__ __forceinline__ uint32_t smem_u32(const void* p) {
    uint32_t a;
    asm("{ .reg .u64 t; cvta.to.shared.u64 t, %1; cvt.u32.u64 %0, t; }" : "=r"(a) : "l"(p));
    return a;
}
#define CP_ASYNC16(dst, src) asm volatile("cp.async.cg.shared.global [%0], [%1], 16;" :: "r"(dst), "l"(src) : "memory")
#define CP_COMMIT()          asm volatile("cp.async.commit_group;" ::: "memory")
#define CP_WAIT0()           asm volatile("cp.async.wait_group 0;" ::: "memory")

__device__ __forceinline__ void ldmatrix_x4(uint32_t* r, uint32_t addr) {
    asm volatile("ldmatrix.sync.aligned.m8n8.x4.shared.b16 {%0,%1,%2,%3}, [%4];"
                 : "=r"(r[0]), "=r"(r[1]), "=r"(r[2]), "=r"(r[3]) : "r"(addr));
}
__device__ __forceinline__ void mma_bf16(float* c, const uint32_t* a, const uint32_t* b) {
    asm volatile("mma.sync.aligned.m16n8k16.row.col.f32.bf16.bf16.f32 "
                 "{%0,%1,%2,%3}, {%4,%5,%6,%7}, {%8,%9}, {%0,%1,%2,%3};"
                 : "+f"(c[0]), "+f"(c[1]), "+f"(c[2]), "+f"(c[3])
                 : "r"(a[0]), "r"(a[1]), "r"(a[2]), "r"(a[3]), "r"(b[0]), "r"(b[1]));
}

// ---------------------------------------------------------------------------
// Fused prep: fp32 -> bf16 pack + squared norms + scratch/out zeroing.
// One warp per row.
// ---------------------------------------------------------------------------
__global__ void prep_kernel(const float* __restrict__ X,
                            const float* __restrict__ Y,
                            float* __restrict__ out, int N, int M) {
    int gtid = blockIdx.x * blockDim.x + threadIdx.x;
    if (gtid < N) g_rowsum[gtid] = 0.0f;
    if (gtid == 0) out[0] = 0.0f;

    int warp = gtid >> 5;
    int lane = threadIdx.x & 31;
    if (warp >= N + M) return;
    const float4* src; uint2* dst; float* nrm; int row;
    if (warp < N) { src = (const float4*)X; dst = (uint2*)g_Xh; nrm = g_x2; row = warp; }
    else          { src = (const float4*)Y; dst = (uint2*)g_Yh; nrm = g_y2; row = warp - N; }

    float4 v1 = src[row * 64 + lane];
    float4 v2 = src[row * 64 + 32 + lane];
    float s = v1.x*v1.x + v1.y*v1.y + v1.z*v1.z + v1.w*v1.w
            + v2.x*v2.x + v2.y*v2.y + v2.z*v2.z + v2.w*v2.w;
#pragma unroll
    for (int o = 16; o; o >>= 1) s += __shfl_xor_sync(0xffffffffu, s, o);
    if (lane == 0) nrm[row] = s;

    uint2 p1, p2;
    asm("cvt.rn.bf16x2.f32 %0, %1, %2;" : "=r"(p1.x) : "f"(v1.y), "f"(v1.x));
    asm("cvt.rn.bf16x2.f32 %0, %1, %2;" : "=r"(p1.y) : "f"(v1.w), "f"(v1.z));
    asm("cvt.rn.bf16x2.f32 %0, %1, %2;" : "=r"(p2.x) : "f"(v2.y), "f"(v2.x));
    asm("cvt.rn.bf16x2.f32 %0, %1, %2;" : "=r"(p2.y) : "f"(v2.w), "f"(v2.z));
    dst[row * 64 + lane]      = p1;
    dst[row * 64 + 32 + lane] = p2;
}

// ---------------------------------------------------------------------------
// Persistent fused distance GEMM via mma.sync bf16.
// Grid ~296 CTAs, each loops over 128x128 tiles (4096 total).
// Per tile: K=256 in 4 chunks of 64, double-buffered cp.async; at the last
// chunk, prefetch the NEXT tile's chunk0 so its prologue hides under this
// tile's epilogue. 8 warps in 2(m) x 4(n), warp tile 64x32.
// ---------------------------------------------------------------------------
#define ROWB   144
#define TILE_B (128 * ROWB)  // 18432 per tile buffer
#define OFF_A  0
#define OFF_B  (2 * TILE_B)
#define OFF_X2 (4 * TILE_B)
#define OFF_Y2 (4 * TILE_B + 512)
#define OFF_RED (4 * TILE_B + 1024)
#define SMEM_DYN (4 * TILE_B + 1536)

__global__ __launch_bounds__(256, 2)
void dist_kernel(int NT) {
    extern __shared__ __align__(16) char smem[];
    const uint32_t sbase = smem_u32(smem);
    float* x2s = (float*)(smem + OFF_X2);
    float* y2s = (float*)(smem + OFF_Y2);
    float* red = (float*)(smem + OFF_RED);

    const int tid  = threadIdx.x;
    const int wid  = tid >> 5;
    const int lane = tid & 31;
    const int iw = (wid >> 2) * 64;
    const int jw = (wid & 3) * 32;
    const int stride = gridDim.x;

    // loader thread mapping (constant across tiles)
    const int lrow0 = tid >> 3;          // rows tid>>3, +32, +64, +96
    const int lq    = tid & 7;

    // ldmatrix address components
    const int aRow = lane & 15;
    const int aColSel = (lane >> 4) * 16;
    const int bRow = ((lane & 16) >> 1) + (lane & 7);
    const int bColSel = ((lane >> 3) & 1) * 16;

    if (tid < 128) red[tid] = 0.0f;

    int t = blockIdx.x;
    if (t >= NT) return;

    // tile -> (iBase, jBase): consecutive CTAs share the j-column group
    auto tile_ptrs = [&](int tt, const uint4*& Ap, const uint4*& Bp) {
        int iIdx = tt & 31, jIdx = tt >> 5;
        Ap = (const uint4*)g_Xh + (size_t)(iIdx * 128) * 32;
        Bp = (const uint4*)g_Yh + (size_t)(jIdx * 128) * 32;
    };

    auto load_chunk = [&](int buf, const uint4* Ap, const uint4* Bp, int kq) {
#pragma unroll
        for (int c = 0; c < 4; c++) {
            int row = lrow0 + c * 32;
            CP_ASYNC16(sbase + OFF_A + buf * TILE_B + row * ROWB + lq * 16,
                       (const void*)(Ap + row * 32 + kq + lq));
        }
#pragma unroll
        for (int c = 0; c < 4; c++) {
            int row = lrow0 + c * 32;
            CP_ASYNC16(sbase + OFF_B + buf * TILE_B + row * ROWB + lq * 16,
                       (const void*)(Bp + row * 32 + kq + lq));
        }
        CP_COMMIT();
    };

    const uint4 *Ag, *Bg;
    tile_ptrs(t, Ag, Bg);
    load_chunk(0, Ag, Bg, 0);

    while (t < NT) {
        const int iBase = (t & 31) * 128;
        const int jBase = (t >> 5) * 128;
        const int tN = t + stride;
        const uint4 *AgN = Ag, *BgN = Bg;
        if (tN < NT) tile_ptrs(tN, AgN, BgN);

        CP_WAIT0();            // chunk0 (prefetched) ready
        __syncthreads();
        // stage norms for this tile (read only in epilogue; syncs in between)
        if (tid < 128) x2s[tid] = g_x2[iBase + tid];
        else           y2s[tid - 128] = g_y2[jBase + tid - 128];

        float acc[4][4][4];
#pragma unroll
        for (int a = 0; a < 4; a++)
#pragma unroll
            for (int b = 0; b < 4; b++)
#pragma unroll
                for (int c = 0; c < 4; c++) acc[a][b][c] = 0.0f;

#pragma unroll
        for (int kt = 0; kt < 4; kt++) {
            const int buf = kt & 1;
            if (kt < 3)       load_chunk(buf ^ 1, Ag, Bg, (kt + 1) * 8);
            else if (tN < NT) load_chunk(0, AgN, BgN, 0);  // next tile prologue

            const uint32_t sA = sbase + OFF_A + buf * TILE_B;
            const uint32_t sB = sbase + OFF_B + buf * TILE_B;
#pragma unroll
            for (int ks = 0; ks < 4; ks++) {
                uint32_t afr[4][4], bfr[4][2];
#pragma unroll
                for (int mf = 0; mf < 4; mf++)
                    ldmatrix_x4(afr[mf], sA + (iw + mf * 16 + aRow) * ROWB
                                            + ks * 32 + aColSel);
#pragma unroll
                for (int np = 0; np < 2; np++) {
                    uint32_t r[4];
                    ldmatrix_x4(r, sB + (jw + np * 16 + bRow) * ROWB
                                      + ks * 32 + bColSel);
                    bfr[2*np][0]   = r[0]; bfr[2*np][1]   = r[1];
                    bfr[2*np+1][0] = r[2]; bfr[2*np+1][1] = r[3];
                }
#pragma unroll
                for (int mf = 0; mf < 4; mf++)
#pragma unroll
                    for (int nf = 0; nf < 4; nf++)
                        mma_bf16(acc[mf][nf], afr[mf], bfr[nf]);
            }
            if (kt < 3) { CP_WAIT0(); __syncthreads(); }
        }
        __syncthreads();   // norms staged + red ready; buffers free for prefetch in flight

        // Epilogue: dist + per-row reduction (next tile's chunk0 loads in flight).
#pragma unroll
        for (int mf = 0; mf < 4; mf++) {
            const int r0 = iw + mf * 16 + (lane >> 2);
            const float x20 = x2s[r0], x21 = x2s[r0 + 8];
            float rs0 = 0.0f, rs1 = 0.0f;
#pragma unroll
            for (int nf = 0; nf < 4; nf++) {
                const int j0 = jw + nf * 8 + (lane & 3) * 2;
                const float y20 = y2s[j0], y21 = y2s[j0 + 1];
                const float* c = acc[mf][nf];
                float d2;
                d2 = fmaxf(fmaf(-2.0f, c[0], x20 + y20), 0.0f) + EPSV; rs0 += d2 * rsqrtf(d2);
                d2 = fmaxf(fmaf(-2.0f, c[1], x20 + y21), 0.0f) + EPSV; rs0 += d2 * rsqrtf(d2);
                d2 = fmaxf(fmaf(-2.0f, c[2], x21 + y20), 0.0f) + EPSV; rs1 += d2 * rsqrtf(d2);
                d2 = fmaxf(fmaf(-2.0f, c[3], x21 + y21), 0.0f) + EPSV; rs1 += d2 * rsqrtf(d2);
            }
            rs0 += __shfl_xor_sync(0xffffffffu, rs0, 1);
            rs0 += __shfl_xor_sync(0xffffffffu, rs0, 2);
            rs1 += __shfl_xor_sync(0xffffffffu, rs1, 1);
            rs1 += __shfl_xor_sync(0xffffffffu, rs1, 2);
            if ((lane & 3) == 0) {
                atomicAdd(&red[r0], rs0);
                atomicAdd(&red[r0 + 8], rs1);
            }
        }
        __syncthreads();
        if (tid < 128) {
            atomicAdd(&g_rowsum[iBase + tid], red[tid]);
            red[tid] = 0.0f;
        }
        t = tN;
        Ag = AgN; Bg = BgN;
    }
}

// ---------------------------------------------------------------------------
// Exact loss, 2D grid (R6 config): block (bx,by): i in [bx*256,+256),
// j in [by*512,+512). 128 blocks.
// ---------------------------------------------------------------------------
__global__ void loss_kernel(float* __restrict__ out, int N, float invM) {
    __shared__ __align__(16) float sj[512];
    __shared__ float wsum[8];
    const int tid = threadIdx.x;
    const int i  = blockIdx.x * 256 + tid;
    const int jb = blockIdx.y * 512;

    for (int tI = tid; tI < 512; tI += 256) sj[tI] = g_rowsum[jb + tI] * invM;
    const float di = g_rowsum[i] * invM;
    __syncthreads();

    float local = 0.0f;
#pragma unroll 4
    for (int j = 0; j < 512; j += 4) {
        float4 v = *(const float4*)&sj[j];
        float df, s;
        df = di - v.x; s = df * df + EPSV; local += s * rsqrtf(s);
        df = di - v.y; s = df * df + EPSV; local += s * rsqrtf(s);
        df = di - v.z; s = df * df + EPSV; local += s * rsqrtf(s);
        df = di - v.w; s = df * df + EPSV; local += s * rsqrtf(s);
    }
#pragma unroll
    for (int o = 16; o; o >>= 1) local += __shfl_xor_sync(0xffffffffu, local, o);
    int lane = tid & 31, warp = tid >> 5;
    if (lane == 0) wsum[warp] = local;
    __syncthreads();
    if (tid == 0) {
        float s = 0.0f;
#pragma unroll
        for (int w = 0; w < 8; w++) s += wsum[w];
        atomicAdd(out, s);
    }
}

// ---------------------------------------------------------------------------
extern "C" void kernel_launch(void* const* d_in, const int* in_sizes, int n_in,
                              void* d_out, int out_size) {
    const float* X = (const float*)d_in[0];
    const float* Y = (const float*)d_in[1];
    float* out = (float*)d_out;
    const int N = in_sizes[0] / D_DIM;   // 4096
    const int M = in_sizes[1] / D_DIM;   // 16384

    static int attr_done = 0;
    if (!attr_done) {
        cudaFuncSetAttribute(dist_kernel,
                             cudaFuncAttributeMaxDynamicSharedMemorySize, SMEM_DYN);
        attr_done = 1;
    }

    prep_kernel<<<((N + M) * 32 + 255) / 256, 256>>>(X, Y, out, N, M);
    const int NT = (M / 128) * (N / 128);   // 4096 tiles
    dist_kernel<<<296, 256, SMEM_DYN>>>(NT);
    dim3 lgrid(N / 256, N / 512);
    loss_kernel<<<lgrid, 256>>>(out, N, 1.0f / (float)M);
}

// round 9
// speedup vs baseline: 1.6930x; 1.1161x over previous
#include <cuda_runtime.h>
#include <cstdint>

#define D_DIM 256
#define N_MAX 4096
#define M_MAX 16384
#define EPSV 1e-12f

// ---------------------------------------------------------------------------
// Scratch (static device arrays; no allocations allowed).
// ---------------------------------------------------------------------------
__device__ float g_x2[N_MAX];
__device__ float g_y2[M_MAX];
__device__ float g_rowsum[N_MAX];
__device__ __align__(16) uint32_t g_Xh[N_MAX * (D_DIM / 2)];   // bf16x2 packed
__device__ __align__(16) uint32_t g_Yh[M_MAX * (D_DIM / 2)];   // bf16x2 packed

// ---------------------------------------------------------------------------
// PTX helpers (arch-portable: ldmatrix / mma.sync / cp.async)
// ---------------------------------------------------------------------------
__device__ __forceinline__ uint32_t smem_u32(const void* p) {
    uint32_t a;
    asm("{ .reg .u64 t; cvta.to.shared.u64 t, %1; cvt.u32.u64 %0, t; }" : "=r"(a) : "l"(p));
    return a;
}
#define CP_ASYNC16(dst, src) asm volatile("cp.async.cg.shared.global [%0], [%1], 16;" :: "r"(dst), "l"(src) : "memory")
#define CP_COMMIT()          asm volatile("cp.async.commit_group;" ::: "memory")
#define CP_WAIT0()           asm volatile("cp.async.wait_group 0;" ::: "memory")

__device__ __forceinline__ void ldmatrix_x4(uint32_t* r, uint32_t addr) {
    asm volatile("ldmatrix.sync.aligned.m8n8.x4.shared.b16 {%0,%1,%2,%3}, [%4];"
                 : "=r"(r[0]), "=r"(r[1]), "=r"(r[2]), "=r"(r[3]) : "r"(addr));
}
__device__ __forceinline__ void mma_bf16(float* c, const uint32_t* a, const uint32_t* b) {
    asm volatile("mma.sync.aligned.m16n8k16.row.col.f32.bf16.bf16.f32 "
                 "{%0,%1,%2,%3}, {%4,%5,%6,%7}, {%8,%9}, {%0,%1,%2,%3};"
                 : "+f"(c[0]), "+f"(c[1]), "+f"(c[2]), "+f"(c[3])
                 : "r"(a[0]), "r"(a[1]), "r"(a[2]), "r"(a[3]), "r"(b[0]), "r"(b[1]));
}

// ---------------------------------------------------------------------------
// Fused prep: fp32 -> bf16 pack + squared norms + scratch/out zeroing.
// One warp per row.  (Measured 7.4us, DRAM-latency bound near its floor.)
// ---------------------------------------------------------------------------
__global__ void prep_kernel(const float* __restrict__ X,
                            const float* __restrict__ Y,
                            float* __restrict__ out, int N, int M) {
    int gtid = blockIdx.x * blockDim.x + threadIdx.x;
    if (gtid < N) g_rowsum[gtid] = 0.0f;
    if (gtid == 0) out[0] = 0.0f;

    int warp = gtid >> 5;
    int lane = threadIdx.x & 31;
    if (warp >= N + M) return;
    const float4* src; uint2* dst; float* nrm; int row;
    if (warp < N) { src = (const float4*)X; dst = (uint2*)g_Xh; nrm = g_x2; row = warp; }
    else          { src = (const float4*)Y; dst = (uint2*)g_Yh; nrm = g_y2; row = warp - N; }

    float4 v1 = src[row * 64 + lane];
    float4 v2 = src[row * 64 + 32 + lane];
    float s = v1.x*v1.x + v1.y*v1.y + v1.z*v1.z + v1.w*v1.w
            + v2.x*v2.x + v2.y*v2.y + v2.z*v2.z + v2.w*v2.w;
#pragma unroll
    for (int o = 16; o; o >>= 1) s += __shfl_xor_sync(0xffffffffu, s, o);
    if (lane == 0) nrm[row] = s;

    uint2 p1, p2;
    asm("cvt.rn.bf16x2.f32 %0, %1, %2;" : "=r"(p1.x) : "f"(v1.y), "f"(v1.x));
    asm("cvt.rn.bf16x2.f32 %0, %1, %2;" : "=r"(p1.y) : "f"(v1.w), "f"(v1.z));
    asm("cvt.rn.bf16x2.f32 %0, %1, %2;" : "=r"(p2.x) : "f"(v2.y), "f"(v2.x));
    asm("cvt.rn.bf16x2.f32 %0, %1, %2;" : "=r"(p2.y) : "f"(v2.w), "f"(v2.z));
    dst[row * 64 + lane]      = p1;
    dst[row * 64 + 32 + lane] = p2;
}

// ---------------------------------------------------------------------------
// Fused distance GEMM via mma.sync bf16 (R6 kernel verbatim: measured 98us).
// CTA 128x128, occ 2; K=256 in 4 chunks of 64, double-buffered cp.async.
// 8 warps in 2(m) x 4(n): warp tile 64x32; B-fragments via ldmatrix.x4 pairs.
// ---------------------------------------------------------------------------
#define ROWB   144
#define TILE_B (128 * ROWB)  // 18432 per tile buffer
#define OFF_A  0
#define OFF_B  (2 * TILE_B)
#define OFF_X2 (4 * TILE_B)
#define OFF_Y2 (4 * TILE_B + 512)
#define OFF_RED (4 * TILE_B + 1024)
#define SMEM_DYN (4 * TILE_B + 1536)

__global__ __launch_bounds__(256, 2)
void dist_kernel(int N, int M) {
    extern __shared__ __align__(16) char smem[];
    const uint32_t sbase = smem_u32(smem);
    float* x2s = (float*)(smem + OFF_X2);
    float* y2s = (float*)(smem + OFF_Y2);
    float* red = (float*)(smem + OFF_RED);

    const int tid  = threadIdx.x;
    const int wid  = tid >> 5;
    const int lane = tid & 31;
    const int iBase = blockIdx.y * 128;
    const int jBase = blockIdx.x * 128;
    const int iw = (wid >> 2) * 64;
    const int jw = (wid & 3) * 32;

    const uint4* Ag = (const uint4*)g_Xh + (size_t)iBase * 32;
    const uint4* Bg = (const uint4*)g_Yh + (size_t)jBase * 32;

    float acc[4][4][4];
#pragma unroll
    for (int a = 0; a < 4; a++)
#pragma unroll
        for (int b = 0; b < 4; b++)
#pragma unroll
            for (int c = 0; c < 4; c++) acc[a][b][c] = 0.0f;

    if (tid < 128) x2s[tid] = g_x2[iBase + tid];
    else           y2s[tid - 128] = g_y2[jBase + tid - 128];
    if (tid < 128) red[tid] = 0.0f;

    auto load_tiles = [&](int buf, int kq) {
#pragma unroll
        for (int t = 0; t < 4; t++) {
            int idx = tid + t * 256;
            int row = idx >> 3, q = idx & 7;
            CP_ASYNC16(sbase + OFF_A + buf * TILE_B + row * ROWB + q * 16,
                       (const void*)(Ag + row * 32 + kq + q));
        }
#pragma unroll
        for (int t = 0; t < 4; t++) {
            int idx = tid + t * 256;
            int row = idx >> 3, q = idx & 7;
            CP_ASYNC16(sbase + OFF_B + buf * TILE_B + row * ROWB + q * 16,
                       (const void*)(Bg + row * 32 + kq + q));
        }
        CP_COMMIT();
    };

    load_tiles(0, 0);
    CP_WAIT0();
    __syncthreads();

    // ldmatrix address components
    const int aRow = lane & 15;
    const int aColSel = (lane >> 4) * 16;
    const int bRow = ((lane & 16) >> 1) + (lane & 7);      // 16-row span
    const int bColSel = ((lane >> 3) & 1) * 16;

#pragma unroll
    for (int kt = 0; kt < 4; kt++) {
        const int buf = kt & 1;
        if (kt < 3) load_tiles(buf ^ 1, (kt + 1) * 8);

        const uint32_t sA = sbase + OFF_A + buf * TILE_B;
        const uint32_t sB = sbase + OFF_B + buf * TILE_B;
#pragma unroll
        for (int ks = 0; ks < 4; ks++) {
            uint32_t afr[4][4], bfr[4][2];
#pragma unroll
            for (int mf = 0; mf < 4; mf++)
                ldmatrix_x4(afr[mf], sA + (iw + mf * 16 + aRow) * ROWB
                                        + ks * 32 + aColSel);
#pragma unroll
            for (int np = 0; np < 2; np++) {
                uint32_t r[4];
                ldmatrix_x4(r, sB + (jw + np * 16 + bRow) * ROWB
                                  + ks * 32 + bColSel);
                bfr[2*np][0]   = r[0]; bfr[2*np][1]   = r[1];
                bfr[2*np+1][0] = r[2]; bfr[2*np+1][1] = r[3];
            }
#pragma unroll
            for (int mf = 0; mf < 4; mf++)
#pragma unroll
                for (int nf = 0; nf < 4; nf++)
                    mma_bf16(acc[mf][nf], afr[mf], bfr[nf]);
        }
        if (kt < 3) { CP_WAIT0(); __syncthreads(); }
    }
    __syncthreads();

    // Epilogue: dist + per-row reduction.
#pragma unroll
    for (int mf = 0; mf < 4; mf++) {
        const int r0 = iw + mf * 16 + (lane >> 2);
        const float x20 = x2s[r0], x21 = x2s[r0 + 8];
        float rs0 = 0.0f, rs1 = 0.0f;
#pragma unroll
        for (int nf = 0; nf < 4; nf++) {
            const int j0 = jw + nf * 8 + (lane & 3) * 2;
            const float y20 = y2s[j0], y21 = y2s[j0 + 1];
            const float* c = acc[mf][nf];
            float d2;
            d2 = fmaxf(fmaf(-2.0f, c[0], x20 + y20), 0.0f) + EPSV; rs0 += d2 * rsqrtf(d2);
            d2 = fmaxf(fmaf(-2.0f, c[1], x20 + y21), 0.0f) + EPSV; rs0 += d2 * rsqrtf(d2);
            d2 = fmaxf(fmaf(-2.0f, c[2], x21 + y20), 0.0f) + EPSV; rs1 += d2 * rsqrtf(d2);
            d2 = fmaxf(fmaf(-2.0f, c[3], x21 + y21), 0.0f) + EPSV; rs1 += d2 * rsqrtf(d2);
        }
        rs0 += __shfl_xor_sync(0xffffffffu, rs0, 1);
        rs0 += __shfl_xor_sync(0xffffffffu, rs0, 2);
        rs1 += __shfl_xor_sync(0xffffffffu, rs1, 1);
        rs1 += __shfl_xor_sync(0xffffffffu, rs1, 2);
        if ((lane & 3) == 0) {
            atomicAdd(&red[r0], rs0);
            atomicAdd(&red[r0 + 8], rs1);
        }
    }
    __syncthreads();
    if (tid < 128) atomicAdd(&g_rowsum[iBase + tid], red[tid]);
}

// ---------------------------------------------------------------------------
// Loss via |diff|: sqrt(diff^2 + 1e-12) ~= |diff|, per-term error <= 1e-6,
// total <= N^2 * 1e-6 ~= 16.7 absolute (~3e-6 rel). Fully parallel positive
// sum — no cancellation (unlike the rank form). No MUFU.
// Block (bx,by): i in [bx*256,+256), j in [by*512,+512). 128 blocks.
// ---------------------------------------------------------------------------
__global__ void loss_kernel(float* __restrict__ out, int N, float invM) {
    __shared__ __align__(16) float sj[512];
    __shared__ float wsum[8];
    const int tid = threadIdx.x;
    const int i  = blockIdx.x * 256 + tid;
    const int jb = blockIdx.y * 512;

    for (int t = tid; t < 512; t += 256) sj[t] = g_rowsum[jb + t] * invM;
    const float di = g_rowsum[i] * invM;
    __syncthreads();

    float local = 0.0f;
#pragma unroll 8
    for (int j = 0; j < 512; j += 4) {
        float4 v = *(const float4*)&sj[j];
        local += fabsf(di - v.x) + fabsf(di - v.y)
               + fabsf(di - v.z) + fabsf(di - v.w);
    }
#pragma unroll
    for (int o = 16; o; o >>= 1) local += __shfl_xor_sync(0xffffffffu, local, o);
    int lane = tid & 31, warp = tid >> 5;
    if (lane == 0) wsum[warp] = local;
    __syncthreads();
    if (tid == 0) {
        float s = 0.0f;
#pragma unroll
        for (int w = 0; w < 8; w++) s += wsum[w];
        atomicAdd(out, s);
    }
}

// ---------------------------------------------------------------------------
extern "C" void kernel_launch(void* const* d_in, const int* in_sizes, int n_in,
                              void* d_out, int out_size) {
    const float* X = (const float*)d_in[0];
    const float* Y = (const float*)d_in[1];
    float* out = (float*)d_out;
    const int N = in_sizes[0] / D_DIM;   // 4096
    const int M = in_sizes[1] / D_DIM;   // 16384

    static int attr_done = 0;
    if (!attr_done) {
        cudaFuncSetAttribute(dist_kernel,
                             cudaFuncAttributeMaxDynamicSharedMemorySize, SMEM_DYN);
        attr_done = 1;
    }

    prep_kernel<<<((N + M) * 32 + 255) / 256, 256>>>(X, Y, out, N, M);
    dim3 grid(M / 128, N / 128);
    dist_kernel<<<grid, 256, SMEM_DYN>>>(N, M);
    dim3 lgrid(N / 256, N / 512);
    loss_kernel<<<lgrid, 256>>>(out, N, 1.0f / (float)M);
}

// round 10
// speedup vs baseline: 1.7161x; 1.0137x over previous
#include <cuda_runtime.h>
#include <cstdint>

#define D_DIM 256
#define N_MAX 4096
#define M_MAX 16384
#define EPSV 1e-12f

// ---------------------------------------------------------------------------
// Scratch (static device arrays; no allocations allowed).
// ---------------------------------------------------------------------------
__device__ float g_x2[N_MAX];
__device__ float g_y2[M_MAX];
__device__ float g_rowsum[N_MAX];
__device__ __align__(16) uint32_t g_Xh[N_MAX * (D_DIM / 2)];   // bf16x2 packed
__device__ __align__(16) uint32_t g_Yh[M_MAX * (D_DIM / 2)];   // bf16x2 packed

// ---------------------------------------------------------------------------
// PTX helpers (arch-portable: ldmatrix / mma.sync / cp.async)
// ---------------------------------------------------------------------------
__device__ __forceinline__ uint32_t smem_u32(const void* p) {
    uint32_t a;
    asm("{ .reg .u64 t; cvta.to.shared.u64 t, %1; cvt.u32.u64 %0, t; }" : "=r"(a) : "l"(p));
    return a;
}
#define CP_ASYNC16(dst, src) asm volatile("cp.async.cg.shared.global [%0], [%1], 16;" :: "r"(dst), "l"(src) : "memory")
#define CP_COMMIT()          asm volatile("cp.async.commit_group;" ::: "memory")
#define CP_WAIT0()           asm volatile("cp.async.wait_group 0;" ::: "memory")

__device__ __forceinline__ void ldmatrix_x4(uint32_t* r, uint32_t addr) {
    asm volatile("ldmatrix.sync.aligned.m8n8.x4.shared.b16 {%0,%1,%2,%3}, [%4];"
                 : "=r"(r[0]), "=r"(r[1]), "=r"(r[2]), "=r"(r[3]) : "r"(addr));
}
__device__ __forceinline__ void mma_bf16(float* c, const uint32_t* a, const uint32_t* b) {
    asm volatile("mma.sync.aligned.m16n8k16.row.col.f32.bf16.bf16.f32 "
                 "{%0,%1,%2,%3}, {%4,%5,%6,%7}, {%8,%9}, {%0,%1,%2,%3};"
                 : "+f"(c[0]), "+f"(c[1]), "+f"(c[2]), "+f"(c[3])
                 : "r"(a[0]), "r"(a[1]), "r"(a[2]), "r"(a[3]), "r"(b[0]), "r"(b[1]));
}

// ---------------------------------------------------------------------------
// Fused prep: fp32 -> bf16 pack + squared norms + scratch/out zeroing.
// TWO rows per warp: each thread issues 4 independent LDG.128 up front
// (MLP 4) before the dependent shuffle chains.
// ---------------------------------------------------------------------------
__global__ void prep_kernel(const float* __restrict__ X,
                            const float* __restrict__ Y,
                            float* __restrict__ out, int N, int M) {
    int gtid = blockIdx.x * blockDim.x + threadIdx.x;
    if (gtid < N) g_rowsum[gtid] = 0.0f;
    if (gtid == 0) out[0] = 0.0f;

    int warp = gtid >> 5;                 // handles rows 2*warp, 2*warp+1
    int lane = threadIdx.x & 31;
    int rowp = warp * 2;
    if (rowp >= N + M) return;
    const float4* src; uint2* dst; float* nrm; int row;
    if (rowp < N) { src = (const float4*)X; dst = (uint2*)g_Xh; nrm = g_x2; row = rowp; }
    else          { src = (const float4*)Y; dst = (uint2*)g_Yh; nrm = g_y2; row = rowp - N; }

    // 4 independent loads, back-to-back
    float4 a1 = src[(row + 0) * 64 + lane];
    float4 a2 = src[(row + 0) * 64 + 32 + lane];
    float4 b1 = src[(row + 1) * 64 + lane];
    float4 b2 = src[(row + 1) * 64 + 32 + lane];

    float sa = a1.x*a1.x + a1.y*a1.y + a1.z*a1.z + a1.w*a1.w
             + a2.x*a2.x + a2.y*a2.y + a2.z*a2.z + a2.w*a2.w;
    float sb = b1.x*b1.x + b1.y*b1.y + b1.z*b1.z + b1.w*b1.w
             + b2.x*b2.x + b2.y*b2.y + b2.z*b2.z + b2.w*b2.w;
#pragma unroll
    for (int o = 16; o; o >>= 1) {
        sa += __shfl_xor_sync(0xffffffffu, sa, o);
        sb += __shfl_xor_sync(0xffffffffu, sb, o);
    }
    if (lane == 0) { nrm[row] = sa; nrm[row + 1] = sb; }

    uint2 p;
    asm("cvt.rn.bf16x2.f32 %0, %1, %2;" : "=r"(p.x) : "f"(a1.y), "f"(a1.x));
    asm("cvt.rn.bf16x2.f32 %0, %1, %2;" : "=r"(p.y) : "f"(a1.w), "f"(a1.z));
    dst[(row + 0) * 64 + lane] = p;
    asm("cvt.rn.bf16x2.f32 %0, %1, %2;" : "=r"(p.x) : "f"(a2.y), "f"(a2.x));
    asm("cvt.rn.bf16x2.f32 %0, %1, %2;" : "=r"(p.y) : "f"(a2.w), "f"(a2.z));
    dst[(row + 0) * 64 + 32 + lane] = p;
    asm("cvt.rn.bf16x2.f32 %0, %1, %2;" : "=r"(p.x) : "f"(b1.y), "f"(b1.x));
    asm("cvt.rn.bf16x2.f32 %0, %1, %2;" : "=r"(p.y) : "f"(b1.w), "f"(b1.z));
    dst[(row + 1) * 64 + lane] = p;
    asm("cvt.rn.bf16x2.f32 %0, %1, %2;" : "=r"(p.x) : "f"(b2.y), "f"(b2.x));
    asm("cvt.rn.bf16x2.f32 %0, %1, %2;" : "=r"(p.y) : "f"(b2.w), "f"(b2.z));
    dst[(row + 1) * 64 + 32 + lane] = p;
}

// ---------------------------------------------------------------------------
// Fused distance GEMM via mma.sync bf16 (R6 mainloop, frozen).
// CTA 128x128, occ 2; K=256 in 4 chunks of 64, double-buffered cp.async.
// 8 warps in 2(m) x 4(n): warp tile 64x32; B-fragments via ldmatrix.x4 pairs.
// Epilogue: direct predicated global atomicAdd (no shared staging).
// ---------------------------------------------------------------------------
#define ROWB   144
#define TILE_B (128 * ROWB)  // 18432 per tile buffer
#define OFF_A  0
#define OFF_B  (2 * TILE_B)
#define OFF_X2 (4 * TILE_B)
#define OFF_Y2 (4 * TILE_B + 512)
#define SMEM_DYN (4 * TILE_B + 1024)

__global__ __launch_bounds__(256, 2)
void dist_kernel(int N, int M) {
    extern __shared__ __align__(16) char smem[];
    const uint32_t sbase = smem_u32(smem);
    float* x2s = (float*)(smem + OFF_X2);
    float* y2s = (float*)(smem + OFF_Y2);

    const int tid  = threadIdx.x;
    const int wid  = tid >> 5;
    const int lane = tid & 31;
    const int iBase = blockIdx.y * 128;
    const int jBase = blockIdx.x * 128;
    const int iw = (wid >> 2) * 64;
    const int jw = (wid & 3) * 32;

    const uint4* Ag = (const uint4*)g_Xh + (size_t)iBase * 32;
    const uint4* Bg = (const uint4*)g_Yh + (size_t)jBase * 32;

    float acc[4][4][4];
#pragma unroll
    for (int a = 0; a < 4; a++)
#pragma unroll
        for (int b = 0; b < 4; b++)
#pragma unroll
            for (int c = 0; c < 4; c++) acc[a][b][c] = 0.0f;

    if (tid < 128) x2s[tid] = g_x2[iBase + tid];
    else           y2s[tid - 128] = g_y2[jBase + tid - 128];

    auto load_tiles = [&](int buf, int kq) {
#pragma unroll
        for (int t = 0; t < 4; t++) {
            int idx = tid + t * 256;
            int row = idx >> 3, q = idx & 7;
            CP_ASYNC16(sbase + OFF_A + buf * TILE_B + row * ROWB + q * 16,
                       (const void*)(Ag + row * 32 + kq + q));
        }
#pragma unroll
        for (int t = 0; t < 4; t++) {
            int idx = tid + t * 256;
            int row = idx >> 3, q = idx & 7;
            CP_ASYNC16(sbase + OFF_B + buf * TILE_B + row * ROWB + q * 16,
                       (const void*)(Bg + row * 32 + kq + q));
        }
        CP_COMMIT();
    };

    load_tiles(0, 0);
    CP_WAIT0();
    __syncthreads();

    // ldmatrix address components
    const int aRow = lane & 15;
    const int aColSel = (lane >> 4) * 16;
    const int bRow = ((lane & 16) >> 1) + (lane & 7);      // 16-row span
    const int bColSel = ((lane >> 3) & 1) * 16;

#pragma unroll
    for (int kt = 0; kt < 4; kt++) {
        const int buf = kt & 1;
        if (kt < 3) load_tiles(buf ^ 1, (kt + 1) * 8);

        const uint32_t sA = sbase + OFF_A + buf * TILE_B;
        const uint32_t sB = sbase + OFF_B + buf * TILE_B;
#pragma unroll
        for (int ks = 0; ks < 4; ks++) {
            uint32_t afr[4][4], bfr[4][2];
#pragma unroll
            for (int mf = 0; mf < 4; mf++)
                ldmatrix_x4(afr[mf], sA + (iw + mf * 16 + aRow) * ROWB
                                        + ks * 32 + aColSel);
#pragma unroll
            for (int np = 0; np < 2; np++) {
                uint32_t r[4];
                ldmatrix_x4(r, sB + (jw + np * 16 + bRow) * ROWB
                                  + ks * 32 + bColSel);
                bfr[2*np][0]   = r[0]; bfr[2*np][1]   = r[1];
                bfr[2*np+1][0] = r[2]; bfr[2*np+1][1] = r[3];
            }
#pragma unroll
            for (int mf = 0; mf < 4; mf++)
#pragma unroll
                for (int nf = 0; nf < 4; nf++)
                    mma_bf16(acc[mf][nf], afr[mf], bfr[nf]);
        }
        if (kt < 3) { CP_WAIT0(); __syncthreads(); }
    }

    // Epilogue: dist + per-row reduction, direct global atomics.
#pragma unroll
    for (int mf = 0; mf < 4; mf++) {
        const int r0 = iw + mf * 16 + (lane >> 2);
        const float x20 = x2s[r0], x21 = x2s[r0 + 8];
        float rs0 = 0.0f, rs1 = 0.0f;
#pragma unroll
        for (int nf = 0; nf < 4; nf++) {
            const int j0 = jw + nf * 8 + (lane & 3) * 2;
            const float y20 = y2s[j0], y21 = y2s[j0 + 1];
            const float* c = acc[mf][nf];
            float d2;
            d2 = fmaxf(fmaf(-2.0f, c[0], x20 + y20), 0.0f) + EPSV; rs0 += d2 * rsqrtf(d2);
            d2 = fmaxf(fmaf(-2.0f, c[1], x20 + y21), 0.0f) + EPSV; rs0 += d2 * rsqrtf(d2);
            d2 = fmaxf(fmaf(-2.0f, c[2], x21 + y20), 0.0f) + EPSV; rs1 += d2 * rsqrtf(d2);
            d2 = fmaxf(fmaf(-2.0f, c[3], x21 + y21), 0.0f) + EPSV; rs1 += d2 * rsqrtf(d2);
        }
        rs0 += __shfl_xor_sync(0xffffffffu, rs0, 1);
        rs0 += __shfl_xor_sync(0xffffffffu, rs0, 2);
        rs1 += __shfl_xor_sync(0xffffffffu, rs1, 1);
        rs1 += __shfl_xor_sync(0xffffffffu, rs1, 2);
        if ((lane & 3) == 0) {
            atomicAdd(&g_rowsum[iBase + r0], rs0);
            atomicAdd(&g_rowsum[iBase + r0 + 8], rs1);
        }
    }
}

// ---------------------------------------------------------------------------
// Loss via |diff|: sqrt(diff^2 + 1e-12) ~= |diff|, total error <= N^2*1e-6
// (~3e-6 rel), fully parallel positive sum. No MUFU.
// Block (bx,by): i in [bx*256,+256), j in [by*512,+512). 128 blocks.
// ---------------------------------------------------------------------------
__global__ void loss_kernel(float* __restrict__ out, int N, float invM) {
    __shared__ __align__(16) float sj[512];
    __shared__ float wsum[8];
    const int tid = threadIdx.x;
    const int i  = blockIdx.x * 256 + tid;
    const int jb = blockIdx.y * 512;

    for (int t = tid; t < 512; t += 256) sj[t] = g_rowsum[jb + t] * invM;
    const float di = g_rowsum[i] * invM;
    __syncthreads();

    float local = 0.0f;
#pragma unroll 8
    for (int j = 0; j < 512; j += 4) {
        float4 v = *(const float4*)&sj[j];
        local += fabsf(di - v.x) + fabsf(di - v.y)
               + fabsf(di - v.z) + fabsf(di - v.w);
    }
#pragma unroll
    for (int o = 16; o; o >>= 1) local += __shfl_xor_sync(0xffffffffu, local, o);
    int lane = tid & 31, warp = tid >> 5;
    if (lane == 0) wsum[warp] = local;
    __syncthreads();
    if (tid == 0) {
        float s = 0.0f;
#pragma unroll
        for (int w = 0; w < 8; w++) s += wsum[w];
        atomicAdd(out, s);
    }
}

// ---------------------------------------------------------------------------
extern "C" void kernel_launch(void* const* d_in, const int* in_sizes, int n_in,
                              void* d_out, int out_size) {
    const float* X = (const float*)d_in[0];
    const float* Y = (const float*)d_in[1];
    float* out = (float*)d_out;
    const int N = in_sizes[0] / D_DIM;   // 4096
    const int M = in_sizes[1] / D_DIM;   // 16384

    static int attr_done = 0;
    if (!attr_done) {
        cudaFuncSetAttribute(dist_kernel,
                             cudaFuncAttributeMaxDynamicSharedMemorySize, SMEM_DYN);
        attr_done = 1;
    }

    prep_kernel<<<((N + M) * 16 + 255) / 256, 256>>>(X, Y, out, N, M);
    dim3 grid(M / 128, N / 128);
    dist_kernel<<<grid, 256, SMEM_DYN>>>(N, M);
    dim3 lgrid(N / 256, N / 512);
    loss_kernel<<<lgrid, 256>>>(out, N, 1.0f / (float)M);
}